// round 7
// baseline (speedup 1.0000x reference)
#include <cuda_runtime.h>

#define BATCH  16
#define H      1024
#define W      1024
#define HW     (H*W)
#define W2     512            // float2 words per row
#define NCHUNK 9
#define CHUNK  115            // 9*115 = 1035 >= 1024 (last chunk clamps)
#define NBLK   (BATCH*NCHUNK) // 144 blocks
#define RING   32
#define RSTR   516            // floats per ring slot per parity
#define SUSZ   528            // 8 left guard + 512 + 8 right guard

__device__ float        g_accum[BATCH * 5];
__device__ unsigned int g_count;

__device__ __forceinline__ int rsl(int s, int d) { return (s + d + RING) & (RING - 1); }

__device__ __forceinline__ void epi(float x, float m, float S3, float S15, float S31,
                                    float& a0, float& a1, float& a2, float& a3, float& a4)
{
    float w = 1.f + 5.f * ( fabsf(S3  * (1.f / 9.f)   - m)
                          + fabsf(S15 * (1.f / 225.f) - m)
                          + fabsf(S31 * (1.f / 961.f) - m) );
    float e   = __expf(-fabsf(x));
    float l   = __logf(1.f + e);
    float bce = fmaxf(x, 0.f) - x * m + l;
    float inv = __fdividef(1.f, 1.f + e);
    float sg  = (x >= 0.f) ? inv : e * inv;
    a0 += w;
    a1 += w * bce;
    a2 += sg * m * w;
    a3 += (sg + m) * w;
    a4 += fabsf(sg - m);
}

__global__ __launch_bounds__(512, 1) void adaptive_loss_main(
    const float* __restrict__ pred, const float* __restrict__ mask, float* __restrict__ out)
{
    extern __shared__ float sm[];
    float* ringE = sm;                        // [slot*RSTR + t]       : P[2t]
    float* ringO = ringE + RING * RSTR;       // [slot*RSTR + 1 + t]   : P[2t+1], [slot*RSTR]=0 guard
    float* sE31  = ringO + RING * RSTR;       // U31 even cols: [8+t], guards [0..7]=0, [520..527]=flat
    float* sO31  = sE31 + SUSZ;
    float* sE15  = sO31 + SUSZ;
    float* sO15  = sE15 + SUSZ;
    float* sE3   = sO15 + SUSZ;
    float* sO3   = sE3  + SUSZ;
    float* swsum = sO3  + SUSZ;               // 2*16
    float* sred  = swsum + 32;                // 16*5
    unsigned int* sflag = (unsigned int*)(sred + 80);

    const int tid  = threadIdx.x;             // owns cols 2*tid, 2*tid+1
    const int lane = tid & 31;
    const int warp = tid >> 5;

    const int b  = blockIdx.x / NCHUNK;
    const int c  = blockIdx.x % NCHUNK;
    const int y0 = c * CHUNK;
    const int rows = (H - y0 < CHUNK) ? (H - y0) : CHUNK;

    const float2* mb2 = (const float2*)(mask + (size_t)b * HW);
    const float2* pb2 = (const float2*)(pred + (size_t)b * HW);

    // one-time guards
    if (tid < RING) ringO[tid * RSTR] = 0.f;
    if (tid >= 64 && tid < 112) {
        int k = tid - 64;                      // 6 arrays x 8 left-guard words
        float* base = (k < 8) ? sE31 : (k < 16) ? sO31 : (k < 24) ? sE15
                    : (k < 32) ? sO15 : (k < 40) ? sE3 : sO3;
        base[k & 7] = 0.f;
    }
    __syncthreads();

    float2 U31 = make_float2(0.f, 0.f), U15 = U31, U3 = U31;
    float a0 = 0.f, a1 = 0.f, a2 = 0.f, a3 = 0.f, a4 = 0.f;
    int sp  = (y0 - 16 + 64) & 31;             // slot of next-written row (y0-16 first)
    int par = 0;

    // ---- priming: rows y0-16 .. y0+14 (j = 0..30), depth-2 prefetch ----
    float2 mA, mB;
    {
        int r0 = y0 - 16, r1 = y0 - 15;
        mA = (r0 >= 0) ? mb2[(size_t)r0 * W2 + tid] : make_float2(0.f, 0.f);
        mB = (r1 >= 0) ? mb2[(size_t)r1 * W2 + tid] : make_float2(0.f, 0.f);
    }
    #pragma unroll 1
    for (int j = 0; j < 31; ++j) {
        int rp = y0 - 14 + j;
        float2 mC = (rp >= 0 && rp < H) ? mb2[(size_t)rp * W2 + tid] : make_float2(0.f, 0.f);

        float2 v = mA; v.y += v.x;
        float tot = v.y;
        #pragma unroll
        for (int d = 1; d < 32; d <<= 1) {
            float t = __shfl_up_sync(0xffffffffu, tot, d);
            if (lane >= d) tot += t;
        }
        float base = tot - v.y;
        if (lane == 31) swsum[par * 16 + warp] = tot;
        __syncthreads();
        float wv = (lane < 16) ? swsum[par * 16 + lane] : 0.f;
        #pragma unroll
        for (int d = 1; d < 16; d <<= 1) {
            float t = __shfl_up_sync(0xffffffffu, wv, d);
            if (lane >= d) wv += t;
        }
        float off = __shfl_sync(0xffffffffu, wv, (warp > 0) ? (warp - 1) : 0);
        if (warp == 0) off = 0.f;
        base += off;
        float Px = v.x + base, Py = v.y + base;
        ringE[sp * RSTR + tid]     = Px;
        ringO[sp * RSTR + 1 + tid] = Py;
        U31.x += Px; U31.y += Py;
        if (j >= 8  && j <= 22) { U15.x += Px; U15.y += Py; }
        if (j >= 14 && j <= 16) { U3.x  += Px; U3.y  += Py; }
        mA = mB; mB = mC;
        sp = (sp + 1) & 31;
        par ^= 1;
    }
    // mA = row y0+15, mB = row y0+16; sp = slot of row y0+15

    float2 pA = pb2[(size_t)y0 * W2 + tid];
    float2 pB = pb2[(size_t)(y0 + 1) * W2 + tid];

    // ---- main loop: rows y0 .. y0+rows-1 ----
    #pragma unroll 1
    for (int i = 0; i < rows; ++i) {
        const int y  = y0 + i;
        const int rm = y + 17, rp = y + 2;
        float2 mC = (rm < H) ? mb2[(size_t)rm * W2 + tid] : make_float2(0.f, 0.f);
        float2 pC = (rp < H) ? pb2[(size_t)rp * W2 + tid] : make_float2(0.f, 0.f);

        // scan of row y+15
        float2 v = mA; v.y += v.x;
        float tot = v.y;
        #pragma unroll
        for (int d = 1; d < 32; d <<= 1) {
            float t = __shfl_up_sync(0xffffffffu, tot, d);
            if (lane >= d) tot += t;
        }
        float base = tot - v.y;
        if (lane == 31) swsum[par * 16 + warp] = tot;
        __syncthreads();                                   // bar 1
        float wv = (lane < 16) ? swsum[par * 16 + lane] : 0.f;
        #pragma unroll
        for (int d = 1; d < 16; d <<= 1) {
            float t = __shfl_up_sync(0xffffffffu, wv, d);
            if (lane >= d) wv += t;
        }
        float off = __shfl_sync(0xffffffffu, wv, (warp > 0) ? (warp - 1) : 0);
        if (warp == 0) off = 0.f;
        base += off;
        float Px = v.x + base, Py = v.y + base;
        ringE[sp * RSTR + tid]     = Px;                   // row y+15
        ringO[sp * RSTR + 1 + tid] = Py;

        const int s16 = rsl(sp, -31), s7 = rsl(sp, -8), s8 = rsl(sp, -23);
        const int s1  = rsl(sp, -14), s2 = rsl(sp, -17), sc = rsl(sp, -15);

        U31.x += Px - ringE[s16 * RSTR + tid];
        U31.y += Py - ringO[s16 * RSTR + 1 + tid];
        U15.x += ringE[s7 * RSTR + tid]     - ringE[s8 * RSTR + tid];
        U15.y += ringO[s7 * RSTR + 1 + tid] - ringO[s8 * RSTR + 1 + tid];
        U3.x  += ringE[s1 * RSTR + tid]     - ringE[s2 * RSTR + tid];
        U3.y  += ringO[s1 * RSTR + 1 + tid] - ringO[s2 * RSTR + 1 + tid];

        sE31[8 + tid] = U31.x; sO31[8 + tid] = U31.y;
        sE15[8 + tid] = U15.x; sO15[8 + tid] = U15.y;
        sE3 [8 + tid] = U3.x;  sO3 [8 + tid] = U3.y;
        if (warp == 15) {
            float g31 = __shfl_sync(0xffffffffu, U31.y, 31);
            float g15 = __shfl_sync(0xffffffffu, U15.y, 31);
            float g3  = __shfl_sync(0xffffffffu, U3.y,  31);
            if (lane < 8)       { sE31[520 + lane] = g31; sE15[520 + lane] = g15; sE3[520 + lane] = g3; }
            else if (lane < 16) { sO31[512 + lane] = g31; sO15[512 + lane] = g15; sO3[512 + lane] = g3; }
        }
        __syncthreads();                                   // bar 2

        // ---- consume row y (cols 2t, 2t+1) ----
        float S31a = sO31[tid + 15] - sE31[tid];           // U[2t+15] - U[2t-16]
        float S31b = sE31[tid + 16] - sO31[tid];           // U[2t+16] - U[2t-15]  (odd col 2(t-8)+1 -> idx 8+t-8 = tid)
        float S15a = sO15[tid + 11] - sE15[tid + 4];       // U[2t+7]  - U[2t-8]
        float S15b = sE15[tid + 12] - sO15[tid + 4];       // U[2t+8]  - U[2t-7]
        float S3a  = U3.y           - sE3 [tid + 7];       // U[2t+1]  - U[2t-2]
        float S3b  = sE3 [tid + 9]  - sO3 [tid + 7];       // U[2t+2]  - U[2t-1]

        float Pm0 = ringE[sc * RSTR + tid];                // P[2t]
        float Pm1 = ringO[sc * RSTR + 1 + tid];            // P[2t+1]
        float Pl  = ringO[sc * RSTR + tid];                // P[2t-1], guard=0 at t=0
        float m0 = Pm0 - Pl, m1 = Pm1 - Pm0;

        epi(pA.x, m0, S3a, S15a, S31a, a0, a1, a2, a3, a4);
        epi(pA.y, m1, S3b, S15b, S31b, a0, a1, a2, a3, a4);

        mA = mB; mB = mC; pA = pB; pB = pC;
        sp = (sp + 1) & 31;
        par ^= 1;
    }

    // ---- block reduction + atomics ----
    #pragma unroll
    for (int d = 16; d > 0; d >>= 1) {
        a0 += __shfl_down_sync(0xffffffffu, a0, d);
        a1 += __shfl_down_sync(0xffffffffu, a1, d);
        a2 += __shfl_down_sync(0xffffffffu, a2, d);
        a3 += __shfl_down_sync(0xffffffffu, a3, d);
        a4 += __shfl_down_sync(0xffffffffu, a4, d);
    }
    if (lane == 0) {
        sred[warp * 5 + 0] = a0; sred[warp * 5 + 1] = a1; sred[warp * 5 + 2] = a2;
        sred[warp * 5 + 3] = a3; sred[warp * 5 + 4] = a4;
    }
    __syncthreads();
    if (warp == 0 && lane < 5) {
        float t = 0.f;
        #pragma unroll
        for (int wq = 0; wq < 16; ++wq) t += sred[wq * 5 + lane];
        atomicAdd(&g_accum[b * 5 + lane], t);
    }

    // ---- last-block finalize ----
    __threadfence();
    if (tid == 0) {
        unsigned int cdone = atomicAdd(&g_count, 1u);
        *sflag = (cdone == (unsigned int)(gridDim.x - 1)) ? 1u : 0u;
    }
    __syncthreads();
    if (*sflag && tid == 0) {
        float vals[BATCH * 5];
        #pragma unroll 1
        for (int i = 0; i < BATCH * 5; ++i) vals[i] = atomicAdd(&g_accum[i], 0.f);
        float mae_total = 0.f;
        for (int bb = 0; bb < BATCH; ++bb) mae_total += vals[bb * 5 + 4];
        const float mae = mae_total / (float)((long long)BATCH * HW);
        float acc = 0.f;
        for (int bb = 0; bb < BATCH; ++bb) {
            float ws = vals[bb * 5 + 0];
            float wb = vals[bb * 5 + 1];
            float it = vals[bb * 5 + 2];
            float un = vals[bb * 5 + 3];
            float wbce = wb / ws;
            float wiou = 1.f - (it + 1.f) / (un - it + 1.f);
            float wmae = mae * ws / (ws - (float)HW);
            acc += 0.7f * (wbce + wiou + wmae);
        }
        out[0] = acc / (float)BATCH;
        #pragma unroll 1
        for (int i = 0; i < BATCH * 5; ++i) g_accum[i] = 0.f;
        __threadfence();
        atomicExch(&g_count, 0u);
    }
}

extern "C" void kernel_launch(void* const* d_in, const int* in_sizes, int n_in,
                              void* d_out, int out_size) {
    const float* pred = (const float*)d_in[0];
    const float* mask = (const float*)d_in[1];
    float* out = (float*)d_out;

    const int smem_bytes = (2 * RING * RSTR + 6 * SUSZ + 32 + 80 + 4) * 4;
    cudaFuncSetAttribute(adaptive_loss_main,
                         cudaFuncAttributeMaxDynamicSharedMemorySize, smem_bytes);
    adaptive_loss_main<<<NBLK, 512, smem_bytes>>>(pred, mask, out);
}